// round 10
// baseline (speedup 1.0000x reference)
#include <cuda_runtime.h>
#include <cuda_bf16.h>
#include <cstdint>

#define T_STEPS 28
#define HID 128
#define IND 28
#define NCLS 10
#define BATCH 8192
#define IG_GROUPS 4
#define IG_RPB (64 * IG_GROUPS)

typedef unsigned long long u64;

// 112 MB scratch: layer-0 input GEMM (+ fused biases), layout [b*T+t][c]
__device__ float g_xw0[BATCH * T_STEPS * HID];

// ---------------- packed fp32x2 helpers (input gemm) ----------------
#define FMA2(acc, a, b) \
    asm("fma.rn.f32x2 %0, %1, %2, %0;" : "+l"(acc) : "l"(a), "l"(b))
#define DUP2(d, s) \
    asm("mov.b64 %0, {%1, %1};" : "=l"(d) : "f"(s))
#define LDS2(a, b, addr) \
    asm("ld.shared.v2.u64 {%0, %1}, [%2];" : "=l"(a), "=l"(b) : "r"(addr))
#define STG2(p, a, b) \
    asm("st.global.v2.u64 [%0], {%1, %2};" :: "l"(p), "l"(a), "l"(b))

__device__ __forceinline__ float ftanh(float x) {
    float e = __expf(2.0f * x);
    return 1.0f - __fdividef(2.0f, e + 1.0f);
}
__device__ __forceinline__ unsigned smaddr(const void* p) {
    return (unsigned)__cvta_generic_to_shared(p);
}

// ---------------- int8 mma helpers ----------------
__device__ __forceinline__ void ldsm4(uint32_t* r, uint32_t a) {
    asm volatile("ldmatrix.sync.aligned.m8n8.x4.shared.b16 {%0,%1,%2,%3}, [%4];"
                 : "=r"(r[0]), "=r"(r[1]), "=r"(r[2]), "=r"(r[3]) : "r"(a));
}
__device__ __forceinline__ void imma(int* d, const uint32_t* a,
                                     uint32_t b0, uint32_t b1) {
    asm volatile("mma.sync.aligned.m16n8k32.row.col.s32.s8.s8.s32 "
                 "{%0,%1,%2,%3}, {%4,%5,%6,%7}, {%8,%9}, {%0,%1,%2,%3};"
                 : "+r"(d[0]), "+r"(d[1]), "+r"(d[2]), "+r"(d[3])
                 : "r"(a[0]), "r"(a[1]), "r"(a[2]), "r"(a[3]), "r"(b0), "r"(b1));
}
// quantize v (|v|<1) into limbs: v ~= (q1*128 + q0) * 2^-14
__device__ __forceinline__ void quant(float v, int& q1, int& q0) {
    float f1 = rintf(v * 128.0f);
    f1 = fminf(fmaxf(f1, -128.0f), 127.0f);
    q1 = (int)f1;
    q0 = __float2int_rn(fmaf(f1, -128.0f, v * 16384.0f));
}
// pack (odd, even) int -> u16 bytes {odd,even} with s8 saturation; even = low byte
__device__ __forceinline__ uint32_t pk2(int odd, int even) {
    uint32_t r;
    asm("cvt.pack.sat.s8.s32.b32 %0, %1, %2, %3;" : "=r"(r)
        : "r"(odd), "r"(even), "r"(0));
    return r;
}
#define STS16(a, v) \
    asm volatile("st.shared.u16 [%0], %1;" :: "r"(a), "h"((unsigned short)(v)) : "memory")
#define BARG(id) asm volatile("bar.sync %0, %1;" :: "r"(id), "r"(64) : "memory")

#define C17 (1.0f / 131072.0f)     // 2^-17
#define C24 (1.0f / 16777216.0f)   // 2^-24

// ---- weight tiles: [n][k] int8, 128 rows x 128B, XOR-swizzled 16B chunks ----
#define WTILE3 16384
#define SM_W   0                       // 6 tiles: W0_1 W0_0 W1_1 W1_0 W2_1 W2_0
#define SM_HX  (6 * WTILE3)            // 98304: 4 pair bufs x 4096 (H1@0, H0@2048)
#define SM_B1  (SM_HX + 4 * 4096)      // 114688: 128 f32
#define SM_FCW (SM_B1 + 512)           // 115200: 1280 f32
#define SM_FCB (SM_FCW + 5120)         // 120320: 16 f32
#define SMEM_TOTAL (SM_FCB + 128)      // 120448

// swizzled byte offset of int8 (n,k) in a weight tile
__device__ __forceinline__ uint32_t wtile_off3(int n, int k) {
    return (uint32_t)n * 128 + ((((uint32_t)k >> 4) ^ ((uint32_t)n & 7)) << 4)
           + ((uint32_t)k & 15);
}

// 3-term limb GEMM: dh += A1*W1 ; dm += A1*W0 + A0*W1.  K=128, N=64 half.
__device__ __forceinline__ void igemm(int (*dh)[4], int (*dm)[4],
                                      const uint32_t (*A1)[4],
                                      const uint32_t (*A0)[4],
                                      uint32_t b1base, uint32_t b0base,
                                      int kb, int xr) {
#pragma unroll
    for (int s = 0; s < 4; s++) {
        const uint32_t coff = (uint32_t)(((2 * s + kb) ^ xr) << 4);
#pragma unroll
        for (int j = 0; j < 4; j++) {
            uint32_t w1[4], w0[4];
            ldsm4(w1, b1base + j * 2048 + coff);
            ldsm4(w0, b0base + j * 2048 + coff);
            imma(dh[2 * j],     A1[s], w1[0], w1[1]);
            imma(dh[2 * j + 1], A1[s], w1[2], w1[3]);
            imma(dm[2 * j],     A1[s], w0[0], w0[1]);
            imma(dm[2 * j + 1], A1[s], w0[2], w0[3]);
            imma(dm[2 * j],     A0[s], w1[0], w1[1]);
            imma(dm[2 * j + 1], A0[s], w1[2], w1[3]);
        }
    }
}

// load A limb fragments (4 k-steps) from a 16x128B exchange tile
__device__ __forceinline__ void ldAi(uint32_t (*f)[4], uint32_t base, int kb, int xr) {
#pragma unroll
    for (int s = 0; s < 4; s++)
        ldsm4(f[s], base + (uint32_t)(((2 * s + kb) ^ xr) << 4));
}

// ---------------------------------------------------------------------------
// Kernel 1: xw0 precompute (FFMA2) — R8 version
// ---------------------------------------------------------------------------
__global__ __launch_bounds__(256, 1) void input_gemm_kernel(
    const float* __restrict__ x, const float* __restrict__ Wih0,
    const float* __restrict__ bih0, const float* __restrict__ bhh0)
{
    __shared__ float Wt[IND * HID];
    __shared__ float xsT[IND * 64];
    __shared__ float bs[HID];

    const int tid = threadIdx.x;
    const int w = tid >> 5, lane = tid & 31;
    const int col0 = 16 * w, r0 = 2 * lane;

    for (int idx = tid; idx < HID * IND; idx += 256) {
        int j = idx / IND, d = idx - j * IND;
        Wt[d * HID + j] = Wih0[idx];
    }
    if (tid < HID) bs[tid] = bih0[tid] + bhh0[tid];
    __syncthreads();

    const unsigned aW = smaddr(Wt) + col0 * 4;
    const unsigned aB = smaddr(bs) + col0 * 4;

    for (int g = 0; g < IG_GROUPS; g++) {
        const int gr0 = blockIdx.x * IG_RPB + g * 64;
        __syncthreads();
        for (int idx = tid; idx < 64 * IND; idx += 256) {
            int r = idx / IND, d = idx - r * IND;
            xsT[d * 64 + r] = x[gr0 * IND + idx];
        }
        __syncthreads();

        u64 acc0[8], acc1[8];
        LDS2(acc0[0], acc0[1], aB);
        LDS2(acc0[2], acc0[3], aB + 16);
        LDS2(acc0[4], acc0[5], aB + 32);
        LDS2(acc0[6], acc0[7], aB + 48);
#pragma unroll
        for (int j = 0; j < 8; j++) acc1[j] = acc0[j];

#pragma unroll
        for (int d = 0; d < IND; d++) {
            float2 hp = *(const float2*)&xsT[d * 64 + r0];
            u64 ha, hb; DUP2(ha, hp.x); DUP2(hb, hp.y);
            u64 w0, w1, w2, w3, w4, w5, w6, w7;
            LDS2(w0, w1, aW + d * 512);
            LDS2(w2, w3, aW + d * 512 + 16);
            LDS2(w4, w5, aW + d * 512 + 32);
            LDS2(w6, w7, aW + d * 512 + 48);
            FMA2(acc0[0], ha, w0); FMA2(acc0[1], ha, w1);
            FMA2(acc0[2], ha, w2); FMA2(acc0[3], ha, w3);
            FMA2(acc0[4], ha, w4); FMA2(acc0[5], ha, w5);
            FMA2(acc0[6], ha, w6); FMA2(acc0[7], ha, w7);
            FMA2(acc1[0], hb, w0); FMA2(acc1[1], hb, w1);
            FMA2(acc1[2], hb, w2); FMA2(acc1[3], hb, w3);
            FMA2(acc1[4], hb, w4); FMA2(acc1[5], hb, w5);
            FMA2(acc1[6], hb, w6); FMA2(acc1[7], hb, w7);
        }

        float* dst0 = &g_xw0[(size_t)(gr0 + r0) * HID + col0];
        float* dst1 = dst0 + HID;
        STG2((u64)dst0,      acc0[0], acc0[1]);
        STG2((u64)dst0 + 16, acc0[2], acc0[3]);
        STG2((u64)dst0 + 32, acc0[4], acc0[5]);
        STG2((u64)dst0 + 48, acc0[6], acc0[7]);
        STG2((u64)dst1,      acc1[0], acc1[1]);
        STG2((u64)dst1 + 16, acc1[2], acc1[3]);
        STG2((u64)dst1 + 32, acc1[4], acc1[5]);
        STG2((u64)dst1 + 48, acc1[6], acc1[7]);
    }
}

// ---------------------------------------------------------------------------
// Kernel 2: int8 IMMA fused recurrence, N-split warp pairs.
// 128 CTAs x 8 warps; pair g owns 16 batch rows; warp u owns 64 hidden cols.
// h exchanged as two int8 limb tiles (H1,H0) per pair.
// ---------------------------------------------------------------------------
__global__ __launch_bounds__(256, 1) void rnn_mma_kernel(
    const float* __restrict__ Whh0, const float* __restrict__ Wih1,
    const float* __restrict__ Whh1, const float* __restrict__ bih1,
    const float* __restrict__ bhh1, const float* __restrict__ fcw,
    const float* __restrict__ fcb,  float* __restrict__ out)
{
    extern __shared__ char smem[];
    const int tid = threadIdx.x;
    const int wid = tid >> 5, lane = tid & 31;
    const int g = wid >> 1, u = wid & 1;

    // ---- prologue: quantize weights into int8 limb tiles ----
    {
        const float* srcs[3] = { Whh0, Wih1, Whh1 };
#pragma unroll
        for (int m = 0; m < 3; m++) {
            char* t1 = smem + SM_W + (2 * m) * WTILE3;      // W1 limb (2^-10)
            char* t0 = t1 + WTILE3;                          // W0 limb (2^-17)
            const float* src = srcs[m];
            for (int idx = tid; idx < HID * HID; idx += 256) {
                int n = idx >> 7, k = idx & 127;
                float wv = src[idx];
                float f1 = fminf(fmaxf(rintf(wv * 1024.0f), -128.0f), 127.0f);
                int i1 = (int)f1;
                int i0 = __float2int_rn(fmaf(f1, -128.0f, wv * 131072.0f));
                uint32_t off = wtile_off3(n, k);
                t1[off] = (char)i1;
                t0[off] = (char)i0;
            }
        }
        float* b1s = (float*)(smem + SM_B1);
        if (tid < HID) b1s[tid] = bih1[tid] + bhh1[tid];
        float* fcws = (float*)(smem + SM_FCW);
        for (int i = tid; i < NCLS * HID; i += 256) fcws[i] = fcw[i];
        if (tid < NCLS) ((float*)(smem + SM_FCB))[tid] = fcb[tid];
    }
    __syncthreads();

    const uint32_t sb = smaddr(smem);
    const int xr  = lane & 7;
    const int kbB = (lane >> 3) & 1;
    const int rowB = (lane & 7) + ((lane >> 4) << 3);
    const int kbA = (lane >> 4) & 1;
    const int rowA = (lane & 7) + (((lane >> 3) & 1) << 3);
    const int gr = lane >> 2, m2 = (lane & 3) * 2;

    // weight fragment bases (include this warp's 64-col half)
    const uint32_t w0_1 = sb + 0 * WTILE3 + (uint32_t)(u * 64 + rowB) * 128;
    const uint32_t w0_0 = sb + 1 * WTILE3 + (uint32_t)(u * 64 + rowB) * 128;
    const uint32_t w1_1 = sb + 2 * WTILE3 + (uint32_t)(u * 64 + rowB) * 128;
    const uint32_t w1_0 = sb + 3 * WTILE3 + (uint32_t)(u * 64 + rowB) * 128;
    const uint32_t w2_1 = sb + 4 * WTILE3 + (uint32_t)(u * 64 + rowB) * 128;
    const uint32_t w2_0 = sb + 5 * WTILE3 + (uint32_t)(u * 64 + rowB) * 128;

    // exchange buffer (per pair): H1 tile @0, H0 tile @2048
    const uint32_t hbuf = sb + SM_HX + (uint32_t)g * 4096;
    const uint32_t hA1 = hbuf + (uint32_t)rowA * 128;
    const uint32_t hA0 = hA1 + 2048;
    const uint32_t hw1 = hbuf + (uint32_t)gr * 128;          // write base, row gr
    const uint32_t hw0 = hw1 + 2048;

    const float* b1s  = (const float*)(smem + SM_B1);
    const float* fcws = (const float*)(smem + SM_FCW);
    const float* fcbs = (const float*)(smem + SM_FCB);
    const int barid = 1 + g;

    const int rowbase = blockIdx.x * 64 + g * 16;
    const float* xb0 = g_xw0 + (size_t)(rowbase + gr) * T_STEPS * HID;
    const float* xb8 = xb0 + (size_t)8 * T_STEPS * HID;

    // A limb fragments: [kstep(4)][4]
    uint32_t A0_1[4][4], A0_0[4][4], A1_1[4][4], A1_0[4][4];
#pragma unroll
    for (int s = 0; s < 4; s++)
#pragma unroll
        for (int q = 0; q < 4; q++) {
            A0_1[s][q] = 0; A0_0[s][q] = 0; A1_1[s][q] = 0; A1_0[s][q] = 0;
        }

    float2 xpf[16];
#pragma unroll
    for (int nb = 0; nb < 8; nb++) {
        int cg = u * 64 + nb * 8 + m2;
        xpf[2 * nb]     = *(const float2*)(xb0 + cg);
        xpf[2 * nb + 1] = *(const float2*)(xb8 + cg);
    }

#pragma unroll 1
    for (int t = 0; t < T_STEPS; t++) {
        // ---------------- layer 0 ----------------
        int dh[8][4], dm[8][4];
#pragma unroll
        for (int i = 0; i < 8; i++)
#pragma unroll
            for (int q = 0; q < 4; q++) { dh[i][q] = 0; dm[i][q] = 0; }

        if (t > 0) igemm(dh, dm, A0_1, A0_0, w0_1, w0_0, kbB, xr);

        // epilogue 0: h0 = tanh(combine + xw0_t) -> quantized limb exchange
#pragma unroll
        for (int nb = 0; nb < 8; nb++) {
            float v0 = ftanh(fmaf((float)dh[nb][0], C17, fmaf((float)dm[nb][0], C24, xpf[2 * nb].x)));
            float v1 = ftanh(fmaf((float)dh[nb][1], C17, fmaf((float)dm[nb][1], C24, xpf[2 * nb].y)));
            float v2 = ftanh(fmaf((float)dh[nb][2], C17, fmaf((float)dm[nb][2], C24, xpf[2 * nb + 1].x)));
            float v3 = ftanh(fmaf((float)dh[nb][3], C17, fmaf((float)dm[nb][3], C24, xpf[2 * nb + 1].y)));
            int q1a, q0a, q1b, q0b, q1c, q0c, q1d, q0d;
            quant(v0, q1a, q0a); quant(v1, q1b, q0b);
            quant(v2, q1c, q0c); quant(v3, q1d, q0d);
            uint32_t off = ((((uint32_t)(u * 4 + (nb >> 1)) ^ gr) << 4)
                            | ((nb & 1) << 3)) + m2;
            STS16(hw1 + off,        pk2(q1b, q1a));
            STS16(hw1 + off + 1024, pk2(q1d, q1c));    // row gr+8
            STS16(hw0 + off,        pk2(q0b, q0a));
            STS16(hw0 + off + 1024, pk2(q0d, q0c));
        }
        BARG(barid);
        ldAi(A0_1, hA1, kbA, xr);
        ldAi(A0_0, hA0, kbA, xr);
        BARG(barid);

        // prefetch next step's x (covered by layer-1 MMA latency)
        if (t + 1 < T_STEPS) {
#pragma unroll
            for (int nb = 0; nb < 8; nb++) {
                int cg = u * 64 + nb * 8 + m2;
                xpf[2 * nb]     = *(const float2*)(xb0 + (size_t)(t + 1) * HID + cg);
                xpf[2 * nb + 1] = *(const float2*)(xb8 + (size_t)(t + 1) * HID + cg);
            }
        }

        // ---------------- layer 1 ----------------
#pragma unroll
        for (int i = 0; i < 8; i++)
#pragma unroll
            for (int q = 0; q < 4; q++) { dh[i][q] = 0; dm[i][q] = 0; }

        igemm(dh, dm, A0_1, A0_0, w1_1, w1_0, kbB, xr);
        if (t > 0) igemm(dh, dm, A1_1, A1_0, w2_1, w2_0, kbB, xr);

        if (t + 1 < T_STEPS) {
            // epilogue 1: h1 = tanh(combine + b1) -> exchange
#pragma unroll
            for (int nb = 0; nb < 8; nb++) {
                int cg = u * 64 + nb * 8 + m2;
                float2 bb = *(const float2*)(b1s + cg);
                float v0 = ftanh(fmaf((float)dh[nb][0], C17, fmaf((float)dm[nb][0], C24, bb.x)));
                float v1 = ftanh(fmaf((float)dh[nb][1], C17, fmaf((float)dm[nb][1], C24, bb.y)));
                float v2 = ftanh(fmaf((float)dh[nb][2], C17, fmaf((float)dm[nb][2], C24, bb.x)));
                float v3 = ftanh(fmaf((float)dh[nb][3], C17, fmaf((float)dm[nb][3], C24, bb.y)));
                int q1a, q0a, q1b, q0b, q1c, q0c, q1d, q0d;
                quant(v0, q1a, q0a); quant(v1, q1b, q0b);
                quant(v2, q1c, q0c); quant(v3, q1d, q0d);
                uint32_t off = ((((uint32_t)(u * 4 + (nb >> 1)) ^ gr) << 4)
                                | ((nb & 1) << 3)) + m2;
                STS16(hw1 + off,        pk2(q1b, q1a));
                STS16(hw1 + off + 1024, pk2(q1d, q1c));
                STS16(hw0 + off,        pk2(q0b, q0a));
                STS16(hw0 + off + 1024, pk2(q0d, q0c));
            }
            BARG(barid);
            ldAi(A1_1, hA1, kbA, xr);
            ldAi(A1_0, hA0, kbA, xr);
            BARG(barid);
        } else {
            // ---------------- FC head ----------------
            float facc[2][NCLS];
#pragma unroll
            for (int r = 0; r < 2; r++)
#pragma unroll
                for (int cl = 0; cl < NCLS; cl++) facc[r][cl] = 0.0f;

#pragma unroll
            for (int nb = 0; nb < 8; nb++) {
                int cg = u * 64 + nb * 8 + m2;
                float2 bb = *(const float2*)(b1s + cg);
                float h0v = ftanh(fmaf((float)dh[nb][0], C17, fmaf((float)dm[nb][0], C24, bb.x)));
                float h1v = ftanh(fmaf((float)dh[nb][1], C17, fmaf((float)dm[nb][1], C24, bb.y)));
                float h8v = ftanh(fmaf((float)dh[nb][2], C17, fmaf((float)dm[nb][2], C24, bb.x)));
                float h9v = ftanh(fmaf((float)dh[nb][3], C17, fmaf((float)dm[nb][3], C24, bb.y)));
#pragma unroll
                for (int cl = 0; cl < NCLS; cl++) {
                    float2 fw = *(const float2*)(fcws + cl * HID + cg);
                    facc[0][cl] += h0v * fw.x + h1v * fw.y;
                    facc[1][cl] += h8v * fw.x + h9v * fw.y;
                }
            }
#pragma unroll
            for (int r = 0; r < 2; r++)
#pragma unroll
                for (int cl = 0; cl < NCLS; cl++) {
                    facc[r][cl] += __shfl_xor_sync(0xffffffff, facc[r][cl], 1);
                    facc[r][cl] += __shfl_xor_sync(0xffffffff, facc[r][cl], 2);
                }

            // per-pair partial reduce through own (now free) exchange buffer
            float* part = (float*)(smem + SM_HX + g * 4096);  // 32 rows x 10 f32
            BARG(barid);                    // all ldAi done before overwrite
            if ((lane & 3) == 0) {
#pragma unroll
                for (int cl = 0; cl < NCLS; cl++) {
                    part[(u * 16 + gr) * NCLS + cl]     = facc[0][cl];
                    part[(u * 16 + gr + 8) * NCLS + cl] = facc[1][cl];
                }
            }
            BARG(barid);
            if (u == 0 && lane < 16) {
                const int grow = rowbase + lane;
#pragma unroll
                for (int cl = 0; cl < NCLS; cl++)
                    out[(size_t)grow * NCLS + cl] =
                        part[lane * NCLS + cl] + part[(16 + lane) * NCLS + cl] + fcbs[cl];
            }
        }
    }
}

// ---------------------------------------------------------------------------
extern "C" void kernel_launch(void* const* d_in, const int* in_sizes, int n_in,
                              void* d_out, int out_size) {
    const float* x    = (const float*)d_in[0];
    const float* Wih0 = (const float*)d_in[1];
    const float* Whh0 = (const float*)d_in[2];
    const float* bih0 = (const float*)d_in[3];
    const float* bhh0 = (const float*)d_in[4];
    const float* Wih1 = (const float*)d_in[5];
    const float* Whh1 = (const float*)d_in[6];
    const float* bih1 = (const float*)d_in[7];
    const float* bhh1 = (const float*)d_in[8];
    const float* fcw  = (const float*)d_in[9];
    const float* fcb  = (const float*)d_in[10];
    float* out = (float*)d_out;

    cudaFuncSetAttribute(rnn_mma_kernel,
                         cudaFuncAttributeMaxDynamicSharedMemorySize, SMEM_TOTAL);

    input_gemm_kernel<<<(BATCH * T_STEPS) / IG_RPB, 256>>>(x, Wih0, bih0, bhh0);
    rnn_mma_kernel<<<BATCH / 64, 256, SMEM_TOTAL>>>(Whh0, Wih1, Whh1,
                                                    bih1, bhh1, fcw, fcb, out);
}

// round 11
// speedup vs baseline: 2.0700x; 2.0700x over previous
#include <cuda_runtime.h>
#include <cuda_bf16.h>
#include <cstdint>

#define T_STEPS 28
#define HID 128
#define IND 28
#define NCLS 10
#define BATCH 8192
#define IG_GROUPS 4
#define IG_RPB (64 * IG_GROUPS)

typedef unsigned long long u64;

// 112 MB scratch: layer-0 input GEMM (+ fused biases), layout [b*T+t][c]
__device__ float g_xw0[BATCH * T_STEPS * HID];

// ---------------- packed fp32x2 helpers (input gemm) ----------------
#define FMA2(acc, a, b) \
    asm("fma.rn.f32x2 %0, %1, %2, %0;" : "+l"(acc) : "l"(a), "l"(b))
#define DUP2(d, s) \
    asm("mov.b64 %0, {%1, %1};" : "=l"(d) : "f"(s))
#define LDS2(a, b, addr) \
    asm("ld.shared.v2.u64 {%0, %1}, [%2];" : "=l"(a), "=l"(b) : "r"(addr))
#define STG2(p, a, b) \
    asm("st.global.v2.u64 [%0], {%1, %2};" :: "l"(p), "l"(a), "l"(b))

__device__ __forceinline__ float ftanh(float x) {
    float e = __expf(2.0f * x);
    return 1.0f - __fdividef(2.0f, e + 1.0f);
}
__device__ __forceinline__ unsigned smaddr(const void* p) {
    return (unsigned)__cvta_generic_to_shared(p);
}

// ---------------- mma.sync helpers ----------------
__device__ __forceinline__ void ldsm4(uint32_t* r, uint32_t a) {
    asm volatile("ldmatrix.sync.aligned.m8n8.x4.shared.b16 {%0,%1,%2,%3}, [%4];"
                 : "=r"(r[0]), "=r"(r[1]), "=r"(r[2]), "=r"(r[3]) : "r"(a));
}
__device__ __forceinline__ void mma16816(float* d, const uint32_t* a,
                                         uint32_t b0, uint32_t b1) {
    asm volatile("mma.sync.aligned.m16n8k16.row.col.f32.bf16.bf16.f32 "
                 "{%0,%1,%2,%3}, {%4,%5,%6,%7}, {%8,%9}, {%0,%1,%2,%3};"
                 : "+f"(d[0]), "+f"(d[1]), "+f"(d[2]), "+f"(d[3])
                 : "r"(a[0]), "r"(a[1]), "r"(a[2]), "r"(a[3]), "r"(b0), "r"(b1));
}
__device__ __forceinline__ uint32_t pack2(float v0, float v1) {
    uint32_t r;
    asm("cvt.rn.bf16x2.f32 %0, %1, %2;" : "=r"(r) : "f"(v1), "f"(v0));
    return r;
}
__device__ __forceinline__ void cvt_pair(float v0, float v1,
                                         uint32_t& hi, uint32_t& lo) {
    uint32_t hp = pack2(v0, v1);
    float e0 = __uint_as_float(hp << 16);
    float e1 = __uint_as_float(hp & 0xffff0000u);
    hi = hp;
    lo = pack2(v0 - e0, v1 - e1);
}
#define STS32(a, v) asm volatile("st.shared.b32 [%0], %1;" :: "r"(a), "r"(v) : "memory")
#define BARG(id) asm volatile("bar.sync %0, %1;" :: "r"(id), "r"(64) : "memory")

// ---- weight tiles: [n][k] bf16, 128 rows x 256B, XOR-swizzled 16B chunks ----
#define WROWB 256
#define WTILE2 (128 * WROWB)          // 32768 B
#define SM_W   0                      // 6 tiles: W0h W0l W1h W1l W2h W2l
#define SM_HX  (6 * WTILE2)           // 196608: 4 group bufs x 8192 (hi@0, lo@4096)
#define SM_B1  (SM_HX + 4 * 8192)     // 229376: 128 f32
#define SMEM_TOTAL (SM_B1 + 512)      // 229888

__device__ __forceinline__ uint32_t wtile_off2(int n, int k) {
    return (uint32_t)n * WROWB + ((((uint32_t)k >> 3) ^ ((uint32_t)n & 7)) << 4)
           + ((uint32_t)k & 7) * 2;
}

// full-N 3-term split-bf16 GEMM: d[16][4] += A(split) @ W(split)^T, K=128, N=128
// 4-accumulator interleave: same-d dependency distance = 4 MMAs.
__device__ __forceinline__ void gemm3f(float (*d)[4],
                                       const uint32_t (*ah)[4],
                                       const uint32_t (*al)[4],
                                       uint32_t baseHi, uint32_t baseLo,
                                       int kb, int xr) {
#pragma unroll
    for (int s = 0; s < 8; s++) {
        const uint32_t coff = (uint32_t)(((2 * s + kb) ^ xr) << 4);
#pragma unroll
        for (int jj = 0; jj < 8; jj += 2) {
            uint32_t bh0[4], bh1[4], bl0[4], bl1[4];
            ldsm4(bh0, baseHi + jj * 4096 + coff);
            ldsm4(bh1, baseHi + (jj + 1) * 4096 + coff);
            ldsm4(bl0, baseLo + jj * 4096 + coff);
            ldsm4(bl1, baseLo + (jj + 1) * 4096 + coff);
            mma16816(d[2 * jj],     ah[s], bh0[0], bh0[1]);
            mma16816(d[2 * jj + 1], ah[s], bh0[2], bh0[3]);
            mma16816(d[2 * jj + 2], ah[s], bh1[0], bh1[1]);
            mma16816(d[2 * jj + 3], ah[s], bh1[2], bh1[3]);
            mma16816(d[2 * jj],     ah[s], bl0[0], bl0[1]);
            mma16816(d[2 * jj + 1], ah[s], bl0[2], bl0[3]);
            mma16816(d[2 * jj + 2], ah[s], bl1[0], bl1[1]);
            mma16816(d[2 * jj + 3], ah[s], bl1[2], bl1[3]);
            mma16816(d[2 * jj],     al[s], bh0[0], bh0[1]);
            mma16816(d[2 * jj + 1], al[s], bh0[2], bh0[3]);
            mma16816(d[2 * jj + 2], al[s], bh1[0], bh1[1]);
            mma16816(d[2 * jj + 3], al[s], bh1[2], bh1[3]);
        }
    }
}

// load full-K A fragments (8 k-steps) from a 16x128 bf16 exchange tile
__device__ __forceinline__ void ldA(uint32_t (*f)[4], uint32_t base, int kb, int xr) {
#pragma unroll
    for (int s = 0; s < 8; s++)
        ldsm4(f[s], base + (uint32_t)(((2 * s + kb) ^ xr) << 4));
}

// ---------------------------------------------------------------------------
// Kernel 1: xw0 precompute (FFMA2) — R8 version, unchanged
// ---------------------------------------------------------------------------
__global__ __launch_bounds__(256, 1) void input_gemm_kernel(
    const float* __restrict__ x, const float* __restrict__ Wih0,
    const float* __restrict__ bih0, const float* __restrict__ bhh0)
{
    __shared__ float Wt[IND * HID];
    __shared__ float xsT[IND * 64];
    __shared__ float bs[HID];

    const int tid = threadIdx.x;
    const int w = tid >> 5, lane = tid & 31;
    const int col0 = 16 * w, r0 = 2 * lane;

    for (int idx = tid; idx < HID * IND; idx += 256) {
        int j = idx / IND, d = idx - j * IND;
        Wt[d * HID + j] = Wih0[idx];
    }
    if (tid < HID) bs[tid] = bih0[tid] + bhh0[tid];
    __syncthreads();

    const unsigned aW = smaddr(Wt) + col0 * 4;
    const unsigned aB = smaddr(bs) + col0 * 4;

    for (int g = 0; g < IG_GROUPS; g++) {
        const int gr0 = blockIdx.x * IG_RPB + g * 64;
        __syncthreads();
        for (int idx = tid; idx < 64 * IND; idx += 256) {
            int r = idx / IND, d = idx - r * IND;
            xsT[d * 64 + r] = x[gr0 * IND + idx];
        }
        __syncthreads();

        u64 acc0[8], acc1[8];
        LDS2(acc0[0], acc0[1], aB);
        LDS2(acc0[2], acc0[3], aB + 16);
        LDS2(acc0[4], acc0[5], aB + 32);
        LDS2(acc0[6], acc0[7], aB + 48);
#pragma unroll
        for (int j = 0; j < 8; j++) acc1[j] = acc0[j];

#pragma unroll
        for (int d = 0; d < IND; d++) {
            float2 hp = *(const float2*)&xsT[d * 64 + r0];
            u64 ha, hb; DUP2(ha, hp.x); DUP2(hb, hp.y);
            u64 w0, w1, w2, w3, w4, w5, w6, w7;
            LDS2(w0, w1, aW + d * 512);
            LDS2(w2, w3, aW + d * 512 + 16);
            LDS2(w4, w5, aW + d * 512 + 32);
            LDS2(w6, w7, aW + d * 512 + 48);
            FMA2(acc0[0], ha, w0); FMA2(acc0[1], ha, w1);
            FMA2(acc0[2], ha, w2); FMA2(acc0[3], ha, w3);
            FMA2(acc0[4], ha, w4); FMA2(acc0[5], ha, w5);
            FMA2(acc0[6], ha, w6); FMA2(acc0[7], ha, w7);
            FMA2(acc1[0], hb, w0); FMA2(acc1[1], hb, w1);
            FMA2(acc1[2], hb, w2); FMA2(acc1[3], hb, w3);
            FMA2(acc1[4], hb, w4); FMA2(acc1[5], hb, w5);
            FMA2(acc1[6], hb, w6); FMA2(acc1[7], hb, w7);
        }

        float* dst0 = &g_xw0[(size_t)(gr0 + r0) * HID + col0];
        float* dst1 = dst0 + HID;
        STG2((u64)dst0,      acc0[0], acc0[1]);
        STG2((u64)dst0 + 16, acc0[2], acc0[3]);
        STG2((u64)dst0 + 32, acc0[4], acc0[5]);
        STG2((u64)dst0 + 48, acc0[6], acc0[7]);
        STG2((u64)dst1,      acc1[0], acc1[1]);
        STG2((u64)dst1 + 16, acc1[2], acc1[3]);
        STG2((u64)dst1 + 32, acc1[4], acc1[5]);
        STG2((u64)dst1 + 48, acc1[6], acc1[7]);
    }
}

// ---------------------------------------------------------------------------
// Kernel 2: warp-specialized fused recurrence.
// Warps 0-3 ("A") = layer-0 producers, warps 4-7 ("B") = layer-1 consumers.
// Group g = {warp g, warp g+4} (co-resident on SMSP g) owns 16 batch rows.
// h0 handed A->B via one 8KB smem tile/group; h1 register-resident in B.
// ---------------------------------------------------------------------------
__global__ __launch_bounds__(256, 1) void rnn_ws_kernel(
    const float* __restrict__ Whh0, const float* __restrict__ Wih1,
    const float* __restrict__ Whh1, const float* __restrict__ bih1,
    const float* __restrict__ bhh1, const float* __restrict__ fcw,
    const float* __restrict__ fcb,  float* __restrict__ out)
{
    extern __shared__ char smem[];
    const int tid = threadIdx.x;
    const int wid = tid >> 5, lane = tid & 31;
    const int isA = (wid < 4);
    const int g = wid & 3;

    // ---- prologue: split weights into bf16 hi/lo swizzled tiles ----
    {
        const float* srcs[3] = { Whh0, Wih1, Whh1 };
#pragma unroll
        for (int m = 0; m < 3; m++) {
            char* hiT = smem + SM_W + (2 * m) * WTILE2;
            char* loT = hiT + WTILE2;
            const float* src = srcs[m];
            for (int idx = tid; idx < HID * HID; idx += 256) {
                int n = idx >> 7, k = idx & 127;
                float wv = src[idx];
                __nv_bfloat16 h = __float2bfloat16(wv);
                float hf = __bfloat162float(h);
                __nv_bfloat16 l = __float2bfloat16(wv - hf);
                uint32_t off = wtile_off2(n, k);
                *(__nv_bfloat16*)(hiT + off) = h;
                *(__nv_bfloat16*)(loT + off) = l;
            }
        }
        float* b1s = (float*)(smem + SM_B1);
        if (tid < HID) b1s[tid] = bih1[tid] + bhh1[tid];
    }
    __syncthreads();

    const uint32_t sb = smaddr(smem);
    const int xr  = lane & 7;
    const int kbB = (lane >> 3) & 1;
    const int rowB = (lane & 7) + ((lane >> 4) << 3);
    const int kbA = (lane >> 4) & 1;
    const int rowA = (lane & 7) + (((lane >> 3) & 1) << 3);
    const int gr = lane >> 2, m2 = (lane & 3) * 2;

    const uint32_t hbuf = sb + SM_HX + (uint32_t)g * 8192;
    const int rowbase = blockIdx.x * 64 + g * 16;
    const int bar1 = 1 + 2 * g, bar2 = 2 + 2 * g;

    if (isA) {
        // =================== A: layer-0 producer ===================
        const uint32_t w0h = sb + 0 * WTILE2 + (uint32_t)rowB * WROWB;
        const uint32_t w0l = sb + 1 * WTILE2 + (uint32_t)rowB * WROWB;
        // h0 write base: row gr, col byte m2*2; +2048 = row gr+8; +4096 = lo tile
        const uint32_t hw = hbuf + (uint32_t)gr * WROWB + (uint32_t)m2 * 2;

        const float* xb0 = g_xw0 + (size_t)(rowbase + gr) * T_STEPS * HID;
        const float* xb8 = xb0 + (size_t)8 * T_STEPS * HID;

        uint32_t a0h[8][4], a0l[8][4];
        float d0[16][4];
        // preload d0 with xw0(t=0)
#pragma unroll
        for (int i = 0; i < 16; i++) {
            float2 p0 = *(const float2*)(xb0 + 8 * i + m2);
            float2 p8 = *(const float2*)(xb8 + 8 * i + m2);
            d0[i][0] = p0.x; d0[i][1] = p0.y; d0[i][2] = p8.x; d0[i][3] = p8.y;
        }

#pragma unroll 1
        for (int t = 0; t < T_STEPS; t++) {
            if (t > 0) gemm3f(d0, a0h, a0l, w0h, w0l, kbB, xr);

            // h0 = tanh(d0); build A-fragments + export tile
#pragma unroll
            for (int s = 0; s < 8; s++) {
                float v0 = ftanh(d0[2 * s][0]);
                float v1 = ftanh(d0[2 * s][1]);
                float v2 = ftanh(d0[2 * s][2]);
                float v3 = ftanh(d0[2 * s][3]);
                float v4 = ftanh(d0[2 * s + 1][0]);
                float v5 = ftanh(d0[2 * s + 1][1]);
                float v6 = ftanh(d0[2 * s + 1][2]);
                float v7 = ftanh(d0[2 * s + 1][3]);
                cvt_pair(v0, v1, a0h[s][0], a0l[s][0]);
                cvt_pair(v2, v3, a0h[s][1], a0l[s][1]);
                cvt_pair(v4, v5, a0h[s][2], a0l[s][2]);
                cvt_pair(v6, v7, a0h[s][3], a0l[s][3]);
                uint32_t offe = (uint32_t)(((2 * s) ^ gr) << 4);      // n-block 2s
                uint32_t offo = (uint32_t)(((2 * s + 1) ^ gr) << 4);  // n-block 2s+1
                STS32(hw + offe,        a0h[s][0]);
                STS32(hw + offe + 2048, a0h[s][1]);
                STS32(hw + offo,        a0h[s][2]);
                STS32(hw + offo + 2048, a0h[s][3]);
                STS32(hw + offe + 4096, a0l[s][0]);
                STS32(hw + offe + 6144, a0l[s][1]);
                STS32(hw + offo + 4096, a0l[s][2]);
                STS32(hw + offo + 6144, a0l[s][3]);
            }

            // preload next xw0 (in flight across the barriers)
            if (t + 1 < T_STEPS) {
                const float* x0n = xb0 + (size_t)(t + 1) * HID;
                const float* x8n = xb8 + (size_t)(t + 1) * HID;
#pragma unroll
                for (int i = 0; i < 16; i++) {
                    float2 p0 = *(const float2*)(x0n + 8 * i + m2);
                    float2 p8 = *(const float2*)(x8n + 8 * i + m2);
                    d0[i][0] = p0.x; d0[i][1] = p0.y; d0[i][2] = p8.x; d0[i][3] = p8.y;
                }
            }
            BARG(bar1);   // h0(t) published
            BARG(bar2);   // B finished reading tile -> safe to overwrite next iter
        }
    } else {
        // =================== B: layer-1 consumer ===================
        const uint32_t w1h = sb + 2 * WTILE2 + (uint32_t)rowB * WROWB;
        const uint32_t w1l = sb + 3 * WTILE2 + (uint32_t)rowB * WROWB;
        const uint32_t w2h = sb + 4 * WTILE2 + (uint32_t)rowB * WROWB;
        const uint32_t w2l = sb + 5 * WTILE2 + (uint32_t)rowB * WROWB;
        const uint32_t hA1 = hbuf + (uint32_t)rowA * WROWB;         // hi tile
        const uint32_t hA0 = hA1 + 4096;                             // lo tile
        const float* b1s = (const float*)(smem + SM_B1);

        uint32_t a0h[8][4], a0l[8][4], a1h[8][4], a1l[8][4];
        float d1[16][4];

#pragma unroll 1
        for (int t = 0; t < T_STEPS; t++) {
            BARG(bar1);                 // wait for h0(t)
            ldA(a0h, hA1, kbA, xr);
            ldA(a0l, hA0, kbA, xr);
            BARG(bar2);                 // tile consumed

#pragma unroll
            for (int i = 0; i < 16; i++)
#pragma unroll
                for (int q = 0; q < 4; q++) d1[i][q] = 0.0f;

            gemm3f(d1, a0h, a0l, w1h, w1l, kbB, xr);
            if (t > 0) gemm3f(d1, a1h, a1l, w2h, w2l, kbB, xr);

            if (t + 1 < T_STEPS) {
                // h1 = tanh(d1 + b1) -> register-resident A-fragments
#pragma unroll
                for (int s = 0; s < 8; s++) {
                    const int c = 16 * s + m2;
                    float2 bb0 = *(const float2*)(b1s + c);
                    float2 bb1 = *(const float2*)(b1s + c + 8);
                    cvt_pair(ftanh(d1[2*s][0] + bb0.x), ftanh(d1[2*s][1] + bb0.y),
                             a1h[s][0], a1l[s][0]);
                    cvt_pair(ftanh(d1[2*s][2] + bb0.x), ftanh(d1[2*s][3] + bb0.y),
                             a1h[s][1], a1l[s][1]);
                    cvt_pair(ftanh(d1[2*s+1][0] + bb1.x), ftanh(d1[2*s+1][1] + bb1.y),
                             a1h[s][2], a1l[s][2]);
                    cvt_pair(ftanh(d1[2*s+1][2] + bb1.x), ftanh(d1[2*s+1][3] + bb1.y),
                             a1h[s][3], a1l[s][3]);
                }
            } else {
                // ---------------- FC head on final h1 ----------------
                float facc0[NCLS], facc1[NCLS];
#pragma unroll
                for (int cl = 0; cl < NCLS; cl++) { facc0[cl] = 0.0f; facc1[cl] = 0.0f; }
#pragma unroll
                for (int s = 0; s < 8; s++) {
                    const int c = 16 * s + m2;
                    float2 bb0 = *(const float2*)(b1s + c);
                    float2 bb1 = *(const float2*)(b1s + c + 8);
                    float h00 = ftanh(d1[2*s][0] + bb0.x);
                    float h01 = ftanh(d1[2*s][1] + bb0.y);
                    float h02 = ftanh(d1[2*s+1][0] + bb1.x);
                    float h03 = ftanh(d1[2*s+1][1] + bb1.y);
                    float h80 = ftanh(d1[2*s][2] + bb0.x);
                    float h81 = ftanh(d1[2*s][3] + bb0.y);
                    float h82 = ftanh(d1[2*s+1][2] + bb1.x);
                    float h83 = ftanh(d1[2*s+1][3] + bb1.y);
#pragma unroll
                    for (int cl = 0; cl < NCLS; cl++) {
                        const float* fr = fcw + cl * HID + c;
                        facc0[cl] += h00 * fr[0] + h01 * fr[1] + h02 * fr[8] + h03 * fr[9];
                        facc1[cl] += h80 * fr[0] + h81 * fr[1] + h82 * fr[8] + h83 * fr[9];
                    }
                }
#pragma unroll
                for (int cl = 0; cl < NCLS; cl++) {
                    facc0[cl] += __shfl_xor_sync(0xffffffff, facc0[cl], 1);
                    facc0[cl] += __shfl_xor_sync(0xffffffff, facc0[cl], 2);
                    facc1[cl] += __shfl_xor_sync(0xffffffff, facc1[cl], 1);
                    facc1[cl] += __shfl_xor_sync(0xffffffff, facc1[cl], 2);
                }
                if ((lane & 3) == 0) {
                    float* o0 = out + (size_t)(rowbase + gr) * NCLS;
                    float* o8 = o0 + (size_t)8 * NCLS;
#pragma unroll
                    for (int cl = 0; cl < NCLS; cl++) {
                        o0[cl] = facc0[cl] + fcb[cl];
                        o8[cl] = facc1[cl] + fcb[cl];
                    }
                }
            }
        }
    }
}

// ---------------------------------------------------------------------------
extern "C" void kernel_launch(void* const* d_in, const int* in_sizes, int n_in,
                              void* d_out, int out_size) {
    const float* x    = (const float*)d_in[0];
    const float* Wih0 = (const float*)d_in[1];
    const float* Whh0 = (const float*)d_in[2];
    const float* bih0 = (const float*)d_in[3];
    const float* bhh0 = (const float*)d_in[4];
    const float* Wih1 = (const float*)d_in[5];
    const float* Whh1 = (const float*)d_in[6];
    const float* bih1 = (const float*)d_in[7];
    const float* bhh1 = (const float*)d_in[8];
    const float* fcw  = (const float*)d_in[9];
    const float* fcb  = (const float*)d_in[10];
    float* out = (float*)d_out;

    cudaFuncSetAttribute(rnn_ws_kernel,
                         cudaFuncAttributeMaxDynamicSharedMemorySize, SMEM_TOTAL);

    input_gemm_kernel<<<(BATCH * T_STEPS) / IG_RPB, 256>>>(x, Wih0, bih0, bhh0);
    rnn_ws_kernel<<<BATCH / 64, 256, SMEM_TOTAL>>>(Whh0, Wih1, Whh1,
                                                   bih1, bhh1, fcw, fcb, out);
}

// round 13
// speedup vs baseline: 2.3214x; 1.1214x over previous
#include <cuda_runtime.h>
#include <cuda_bf16.h>
#include <cstdint>

#define T_STEPS 28
#define HID 128
#define IND 28
#define NCLS 10
#define BATCH 8192
#define IG_GROUPS 4
#define IG_RPB (64 * IG_GROUPS)

typedef unsigned long long u64;

// 112 MB scratch: layer-0 input GEMM (+ fused biases), layout [b*T+t][c]
__device__ float g_xw0[BATCH * T_STEPS * HID];

// ---------------- packed fp32x2 helpers (input gemm) ----------------
#define FMA2(acc, a, b) \
    asm("fma.rn.f32x2 %0, %1, %2, %0;" : "+l"(acc) : "l"(a), "l"(b))
#define DUP2(d, s) \
    asm("mov.b64 %0, {%1, %1};" : "=l"(d) : "f"(s))
#define LDS2(a, b, addr) \
    asm("ld.shared.v2.u64 {%0, %1}, [%2];" : "=l"(a), "=l"(b) : "r"(addr))
#define STG2(p, a, b) \
    asm("st.global.v2.u64 [%0], {%1, %2};" :: "l"(p), "l"(a), "l"(b))

__device__ __forceinline__ float ftanh(float x) {
    float e = __expf(2.0f * x);
    return 1.0f - __fdividef(2.0f, e + 1.0f);
}
__device__ __forceinline__ unsigned smaddr(const void* p) {
    return (unsigned)__cvta_generic_to_shared(p);
}

// ---------------- mma.sync helpers ----------------
__device__ __forceinline__ void ldsm4(uint32_t* r, uint32_t a) {
    asm volatile("ldmatrix.sync.aligned.m8n8.x4.shared.b16 {%0,%1,%2,%3}, [%4];"
                 : "=r"(r[0]), "=r"(r[1]), "=r"(r[2]), "=r"(r[3]) : "r"(a));
}
__device__ __forceinline__ void mma16816(float* d, const uint32_t* a,
                                         uint32_t b0, uint32_t b1) {
    asm volatile("mma.sync.aligned.m16n8k16.row.col.f32.bf16.bf16.f32 "
                 "{%0,%1,%2,%3}, {%4,%5,%6,%7}, {%8,%9}, {%0,%1,%2,%3};"
                 : "+f"(d[0]), "+f"(d[1]), "+f"(d[2]), "+f"(d[3])
                 : "r"(a[0]), "r"(a[1]), "r"(a[2]), "r"(a[3]), "r"(b0), "r"(b1));
}
__device__ __forceinline__ uint32_t pack2(float v0, float v1) {
    uint32_t r;
    asm("cvt.rn.bf16x2.f32 %0, %1, %2;" : "=r"(r) : "f"(v1), "f"(v0));
    return r;
}
__device__ __forceinline__ void cvt_pair(float v0, float v1,
                                         uint32_t& hi, uint32_t& lo) {
    uint32_t hp = pack2(v0, v1);
    float e0 = __uint_as_float(hp << 16);
    float e1 = __uint_as_float(hp & 0xffff0000u);
    hi = hp;
    lo = pack2(v0 - e0, v1 - e1);
}
#define STS32(a, v) asm volatile("st.shared.b32 [%0], %1;" :: "r"(a), "r"(v) : "memory")
#define BARQ(id) asm volatile("bar.sync %0, %1;" :: "r"(id), "r"(128) : "memory")

// ---- weight tiles: [n][k] bf16, 128 rows x 256B, XOR-swizzled 16B chunks ----
#define WROWB 256
#define WTILE2 (128 * WROWB)          // 32768 B
#define SM_W   0                      // 6 tiles: W0h W0l W1h W1l W2h W2l
#define SM_HX  (6 * WTILE2)           // 196608: 4 quad bufs x 8192 (hi@0, lo@4096)
#define SM_B1  (SM_HX + 4 * 8192)     // 229376: 128 f32
#define SMEM_TOTAL (SM_B1 + 512)      // 229888

__device__ __forceinline__ uint32_t wtile_off2(int n, int k) {
    return (uint32_t)n * WROWB + ((((uint32_t)k >> 3) ^ ((uint32_t)n & 7)) << 4)
           + ((uint32_t)k & 7) * 2;
}

// quarter-N 3-term split-bf16 GEMM: d[4][4] += A(split) @ W_32col(split)^T.
// A fragments loaded on demand from the quad exchange tile (aHi/aLo bases).
// Same-accumulator dependency distance = 4 MMAs.
__device__ __forceinline__ void gemm3q(float (*d)[4],
                                       uint32_t aHi, uint32_t aLo,
                                       uint32_t bHi, uint32_t bLo,
                                       int kbA, int kbB, int xr) {
#pragma unroll
    for (int s = 0; s < 8; s++) {
        const uint32_t aoff = (uint32_t)(((2 * s + kbA) ^ xr) << 4);
        const uint32_t boff = (uint32_t)(((2 * s + kbB) ^ xr) << 4);
        uint32_t ah[4], al[4], bh0[4], bh1[4], bl0[4], bl1[4];
        ldsm4(ah, aHi + aoff);
        ldsm4(al, aLo + aoff);
        ldsm4(bh0, bHi + boff);
        ldsm4(bh1, bHi + 4096 + boff);
        ldsm4(bl0, bLo + boff);
        ldsm4(bl1, bLo + 4096 + boff);
        mma16816(d[0], ah, bh0[0], bh0[1]);
        mma16816(d[1], ah, bh0[2], bh0[3]);
        mma16816(d[2], ah, bh1[0], bh1[1]);
        mma16816(d[3], ah, bh1[2], bh1[3]);
        mma16816(d[0], ah, bl0[0], bl0[1]);
        mma16816(d[1], ah, bl0[2], bl0[3]);
        mma16816(d[2], ah, bl1[0], bl1[1]);
        mma16816(d[3], ah, bl1[2], bl1[3]);
        mma16816(d[0], al, bh0[0], bh0[1]);
        mma16816(d[1], al, bh0[2], bh0[3]);
        mma16816(d[2], al, bh1[0], bh1[1]);
        mma16816(d[3], al, bh1[2], bh1[3]);
    }
}

// ---------------------------------------------------------------------------
// Kernel 1: xw0 precompute (FFMA2) — R8 version, unchanged
// ---------------------------------------------------------------------------
__global__ __launch_bounds__(256, 1) void input_gemm_kernel(
    const float* __restrict__ x, const float* __restrict__ Wih0,
    const float* __restrict__ bih0, const float* __restrict__ bhh0)
{
    __shared__ float Wt[IND * HID];
    __shared__ float xsT[IND * 64];
    __shared__ float bs[HID];

    const int tid = threadIdx.x;
    const int w = tid >> 5, lane = tid & 31;
    const int col0 = 16 * w, r0 = 2 * lane;

    for (int idx = tid; idx < HID * IND; idx += 256) {
        int j = idx / IND, d = idx - j * IND;
        Wt[d * HID + j] = Wih0[idx];
    }
    if (tid < HID) bs[tid] = bih0[tid] + bhh0[tid];
    __syncthreads();

    const unsigned aW = smaddr(Wt) + col0 * 4;
    const unsigned aB = smaddr(bs) + col0 * 4;

    for (int g = 0; g < IG_GROUPS; g++) {
        const int gr0 = blockIdx.x * IG_RPB + g * 64;
        __syncthreads();
        for (int idx = tid; idx < 64 * IND; idx += 256) {
            int r = idx / IND, d = idx - r * IND;
            xsT[d * 64 + r] = x[gr0 * IND + idx];
        }
        __syncthreads();

        u64 acc0[8], acc1[8];
        LDS2(acc0[0], acc0[1], aB);
        LDS2(acc0[2], acc0[3], aB + 16);
        LDS2(acc0[4], acc0[5], aB + 32);
        LDS2(acc0[6], acc0[7], aB + 48);
#pragma unroll
        for (int j = 0; j < 8; j++) acc1[j] = acc0[j];

#pragma unroll
        for (int d = 0; d < IND; d++) {
            float2 hp = *(const float2*)&xsT[d * 64 + r0];
            u64 ha, hb; DUP2(ha, hp.x); DUP2(hb, hp.y);
            u64 w0, w1, w2, w3, w4, w5, w6, w7;
            LDS2(w0, w1, aW + d * 512);
            LDS2(w2, w3, aW + d * 512 + 16);
            LDS2(w4, w5, aW + d * 512 + 32);
            LDS2(w6, w7, aW + d * 512 + 48);
            FMA2(acc0[0], ha, w0); FMA2(acc0[1], ha, w1);
            FMA2(acc0[2], ha, w2); FMA2(acc0[3], ha, w3);
            FMA2(acc0[4], ha, w4); FMA2(acc0[5], ha, w5);
            FMA2(acc0[6], ha, w6); FMA2(acc0[7], ha, w7);
            FMA2(acc1[0], hb, w0); FMA2(acc1[1], hb, w1);
            FMA2(acc1[2], hb, w2); FMA2(acc1[3], hb, w3);
            FMA2(acc1[4], hb, w4); FMA2(acc1[5], hb, w5);
            FMA2(acc1[6], hb, w6); FMA2(acc1[7], hb, w7);
        }

        float* dst0 = &g_xw0[(size_t)(gr0 + r0) * HID + col0];
        float* dst1 = dst0 + HID;
        STG2((u64)dst0,      acc0[0], acc0[1]);
        STG2((u64)dst0 + 16, acc0[2], acc0[3]);
        STG2((u64)dst0 + 32, acc0[4], acc0[5]);
        STG2((u64)dst0 + 48, acc0[6], acc0[7]);
        STG2((u64)dst1,      acc1[0], acc1[1]);
        STG2((u64)dst1 + 16, acc1[2], acc1[3]);
        STG2((u64)dst1 + 32, acc1[4], acc1[5]);
        STG2((u64)dst1 + 48, acc1[6], acc1[7]);
    }
}

// ---------------------------------------------------------------------------
// Kernel 2: fused recurrence, 16 warps (512 thr), quad-split N.
// Quad q (warps 4q..4q+3) owns 16 batch rows; warp u owns cols 32u..32u+31.
// One 8KB rotating exchange buffer per quad carries h0 then h1 each step.
// ---------------------------------------------------------------------------
__global__ __launch_bounds__(512, 1) void rnn_mma_kernel(
    const float* __restrict__ Whh0, const float* __restrict__ Wih1,
    const float* __restrict__ Whh1, const float* __restrict__ bih1,
    const float* __restrict__ bhh1, const float* __restrict__ fcw,
    const float* __restrict__ fcb,  float* __restrict__ out)
{
    extern __shared__ char smem[];
    const int tid = threadIdx.x;
    const int wid = tid >> 5, lane = tid & 31;
    const int q = wid >> 2, u = wid & 3;

    // ---- prologue: split weights into bf16 hi/lo swizzled tiles ----
    {
        const float* srcs[3] = { Whh0, Wih1, Whh1 };
#pragma unroll
        for (int m = 0; m < 3; m++) {
            char* hiT = smem + SM_W + (2 * m) * WTILE2;
            char* loT = hiT + WTILE2;
            const float* src = srcs[m];
            for (int idx = tid; idx < HID * HID; idx += 512) {
                int n = idx >> 7, k = idx & 127;
                float wv = src[idx];
                __nv_bfloat16 h = __float2bfloat16(wv);
                float hf = __bfloat162float(h);
                __nv_bfloat16 l = __float2bfloat16(wv - hf);
                uint32_t off = wtile_off2(n, k);
                *(__nv_bfloat16*)(hiT + off) = h;
                *(__nv_bfloat16*)(loT + off) = l;
            }
        }
        float* b1s = (float*)(smem + SM_B1);
        if (tid < HID) b1s[tid] = bih1[tid] + bhh1[tid];
    }
    __syncthreads();

    const uint32_t sb = smaddr(smem);
    const int xr  = lane & 7;
    const int kbB = (lane >> 3) & 1;
    const int rowB = (lane & 7) + ((lane >> 4) << 3);
    const int kbA = (lane >> 4) & 1;
    const int rowA = (lane & 7) + (((lane >> 3) & 1) << 3);
    const int gr = lane >> 2, m2 = (lane & 3) * 2;

    // weight fragment bases (this warp's 32-col slice)
    const uint32_t w0h = sb + 0 * WTILE2 + (uint32_t)(u * 32 + rowB) * WROWB;
    const uint32_t w0l = sb + 1 * WTILE2 + (uint32_t)(u * 32 + rowB) * WROWB;
    const uint32_t w1h = sb + 2 * WTILE2 + (uint32_t)(u * 32 + rowB) * WROWB;
    const uint32_t w1l = sb + 3 * WTILE2 + (uint32_t)(u * 32 + rowB) * WROWB;
    const uint32_t w2h = sb + 4 * WTILE2 + (uint32_t)(u * 32 + rowB) * WROWB;
    const uint32_t w2l = sb + 5 * WTILE2 + (uint32_t)(u * 32 + rowB) * WROWB;

    // quad exchange buffer: hi tile @0, lo tile @4096
    const uint32_t hbuf = sb + SM_HX + (uint32_t)q * 8192;
    const uint32_t hA1 = hbuf + (uint32_t)rowA * WROWB;
    const uint32_t hA0 = hA1 + 4096;
    const uint32_t hw = hbuf + (uint32_t)gr * WROWB + (uint32_t)m2 * 2;

    const float* b1s = (const float*)(smem + SM_B1);
    const int barid = 1 + q;

    const int rowbase = blockIdx.x * 64 + q * 16;
    const float* xb0 = g_xw0 + (size_t)(rowbase + gr) * T_STEPS * HID;
    const float* xb8 = xb0 + (size_t)8 * T_STEPS * HID;

    // persistent accumulators
    float d0[4][4], d1[4][4];
#pragma unroll
    for (int nb = 0; nb < 4; nb++) {
        const int cg = u * 32 + nb * 8 + m2;
        float2 p0 = *(const float2*)(xb0 + cg);   // x(t=0)
        float2 p8 = *(const float2*)(xb8 + cg);
        d0[nb][0] = p0.x; d0[nb][1] = p0.y; d0[nb][2] = p8.x; d0[nb][3] = p8.y;
#pragma unroll
        for (int qq = 0; qq < 4; qq++) d1[nb][qq] = 0.0f;
    }

#pragma unroll 1
    for (int t = 0; t < T_STEPS; t++) {
        // ---- epi0: h0(t) = tanh(d0) -> publish to quad buffer ----
#pragma unroll
        for (int nb = 0; nb < 4; nb++) {
            float v0 = ftanh(d0[nb][0]);
            float v1 = ftanh(d0[nb][1]);
            float v2 = ftanh(d0[nb][2]);
            float v3 = ftanh(d0[nb][3]);
            uint32_t hi0, lo0, hi8, lo8;
            cvt_pair(v0, v1, hi0, lo0);
            cvt_pair(v2, v3, hi8, lo8);
            uint32_t off = (uint32_t)((((u * 4 + nb)) ^ gr) << 4);
            STS32(hw + off,        hi0);
            STS32(hw + off + 2048, hi8);
            STS32(hw + off + 4096, lo0);
            STS32(hw + off + 6144, lo8);
        }
        BARQ(barid);                 // h0(t) visible to quad

        // ---- layer1 term 1: d1 += h0(t) @ Wih1^T ----
        gemm3q(d1, hA1, hA0, w1h, w1l, kbA, kbB, xr);

        // ---- next-step layer0: d0 = x(t+1) + h0(t) @ Whh0^T ----
        if (t + 1 < T_STEPS) {
#pragma unroll
            for (int nb = 0; nb < 4; nb++) {
                const int cg = u * 32 + nb * 8 + m2;
                float2 p0 = *(const float2*)(xb0 + (size_t)(t + 1) * HID + cg);
                float2 p8 = *(const float2*)(xb8 + (size_t)(t + 1) * HID + cg);
                d0[nb][0] = p0.x; d0[nb][1] = p0.y; d0[nb][2] = p8.x; d0[nb][3] = p8.y;
            }
            gemm3q(d0, hA1, hA0, w0h, w0l, kbA, kbB, xr);
        }
        BARQ(barid);                 // h0 buffer consumed by all quad warps

        if (t + 1 < T_STEPS) {
            // ---- epi1: h1(t) = tanh(d1 + b1) -> publish ----
#pragma unroll
            for (int nb = 0; nb < 4; nb++) {
                const int cg = u * 32 + nb * 8 + m2;
                float2 bb = *(const float2*)(b1s + cg);
                float v0 = ftanh(d1[nb][0] + bb.x);
                float v1 = ftanh(d1[nb][1] + bb.y);
                float v2 = ftanh(d1[nb][2] + bb.x);
                float v3 = ftanh(d1[nb][3] + bb.y);
                uint32_t hi0, lo0, hi8, lo8;
                cvt_pair(v0, v1, hi0, lo0);
                cvt_pair(v2, v3, hi8, lo8);
                uint32_t off = (uint32_t)((((u * 4 + nb)) ^ gr) << 4);
                STS32(hw + off,        hi0);
                STS32(hw + off + 2048, hi8);
                STS32(hw + off + 4096, lo0);
                STS32(hw + off + 6144, lo8);
            }
            BARQ(barid);             // h1(t) visible

            // ---- start next step's W2 term: d1 = h1(t) @ Whh1^T ----
#pragma unroll
            for (int nb = 0; nb < 4; nb++)
#pragma unroll
                for (int qq = 0; qq < 4; qq++) d1[nb][qq] = 0.0f;
            gemm3q(d1, hA1, hA0, w2h, w2l, kbA, kbB, xr);
            BARQ(barid);             // h1 buffer consumed
        } else {
            // ---- FC head: out = tanh(d1 + b1) @ fc_w^T + fc_b ----
            float facc0[NCLS], facc1[NCLS];
#pragma unroll
            for (int cl = 0; cl < NCLS; cl++) { facc0[cl] = 0.0f; facc1[cl] = 0.0f; }
#pragma unroll
            for (int nb = 0; nb < 4; nb++) {
                const int cg = u * 32 + nb * 8 + m2;
                float2 bb = *(const float2*)(b1s + cg);
                float h00 = ftanh(d1[nb][0] + bb.x);
                float h01 = ftanh(d1[nb][1] + bb.y);
                float h80 = ftanh(d1[nb][2] + bb.x);
                float h81 = ftanh(d1[nb][3] + bb.y);
#pragma unroll
                for (int cl = 0; cl < NCLS; cl++) {
                    float2 fw = *(const float2*)(fcw + cl * HID + cg);
                    facc0[cl] += h00 * fw.x + h01 * fw.y;
                    facc1[cl] += h80 * fw.x + h81 * fw.y;
                }
            }
#pragma unroll
            for (int cl = 0; cl < NCLS; cl++) {
                facc0[cl] += __shfl_xor_sync(0xffffffff, facc0[cl], 1);
                facc0[cl] += __shfl_xor_sync(0xffffffff, facc0[cl], 2);
                facc1[cl] += __shfl_xor_sync(0xffffffff, facc1[cl], 1);
                facc1[cl] += __shfl_xor_sync(0xffffffff, facc1[cl], 2);
            }
            // quad-level reduce through the (free) exchange buffer
            float* part = (float*)(smem + SM_HX + q * 8192);  // [u][16 rows][10]
            if ((lane & 3) == 0) {
#pragma unroll
                for (int cl = 0; cl < NCLS; cl++) {
                    part[(u * 16 + gr) * NCLS + cl]     = facc0[cl];
                    part[(u * 16 + gr + 8) * NCLS + cl] = facc1[cl];
                }
            }
            BARQ(barid);
            if (u == 0 && lane < 16) {
                const int grow = rowbase + lane;
#pragma unroll
                for (int cl = 0; cl < NCLS; cl++) {
                    float s = part[lane * NCLS + cl]
                            + part[(16 + lane) * NCLS + cl]
                            + part[(32 + lane) * NCLS + cl]
                            + part[(48 + lane) * NCLS + cl];
                    out[(size_t)grow * NCLS + cl] = s + fcb[cl];
                }
            }
        }
    }
}

// ---------------------------------------------------------------------------
extern "C" void kernel_launch(void* const* d_in, const int* in_sizes, int n_in,
                              void* d_out, int out_size) {
    const float* x    = (const float*)d_in[0];
    const float* Wih0 = (const float*)d_in[1];
    const float* Whh0 = (const float*)d_in[2];
    const float* bih0 = (const float*)d_in[3];
    const float* bhh0 = (const float*)d_in[4];
    const float* Wih1 = (const float*)d_in[5];
    const float* Whh1 = (const float*)d_in[6];
    const float* bih1 = (const float*)d_in[7];
    const float* bhh1 = (const float*)d_in[8];
    const float* fcw  = (const float*)d_in[9];
    const float* fcb  = (const float*)d_in[10];
    float* out = (float*)d_out;

    cudaFuncSetAttribute(rnn_mma_kernel,
                         cudaFuncAttributeMaxDynamicSharedMemorySize, SMEM_TOTAL);

    input_gemm_kernel<<<(BATCH * T_STEPS) / IG_RPB, 256>>>(x, Wih0, bih0, bhh0);
    rnn_mma_kernel<<<BATCH / 64, 512, SMEM_TOTAL>>>(Whh0, Wih1, Whh1,
                                                    bih1, bhh1, fcw, fcb, out);
}